// round 8
// baseline (speedup 1.0000x reference)
#include <cuda_runtime.h>
#include <cuda_bf16.h>
#include <cstdint>

// ---------------------------------------------------------------------------
// MeshUpConv: 3x SplineConv (kernel 3x3, degree 2, open spline) on GB300.
//
// R7 -> R8:
//   * GEMM blocks split in N: 64 rows x 160 cols per CTA (half = bid&1),
//     smem 129KB -> 64.6KB => 2 CTAs/SM, grid 296 -> wave-quantization
//     critical path 3x(128x320) -> 1.5x equivalent. launch_bounds(256,2).
//   * scan2 parallelized (serial 1-thread loop was 7.9us).
// ---------------------------------------------------------------------------

#define NMAX  50000
#define EMAX  400000
#define CKOUT 288          // K * C_OUT = 9 * 32
#define NCOLS 320          // 288 Y cols + 32 self cols

__device__ float g_Y[(size_t)NMAX * CKOUT];
__device__ float g_agg1[(size_t)NMAX * 32];
__device__ float g_agg2[(size_t)NMAX * 32];

// sort scratch
__device__ int    g_hist[NMAX];
__device__ int    g_off[NMAX];
__device__ int    g_bsum[128];
__device__ int2   g_se[EMAX];     // sorted (src, dst)
__device__ float2 g_sp[EMAX];     // sorted pseudo

// ---- helpers --------------------------------------------------------------
__device__ __forceinline__ uint32_t pack_bf16(float a, float b) {
    __nv_bfloat162 t = __floats2bfloat162_rn(a, b);
    return *reinterpret_cast<uint32_t*>(&t);
}
__device__ __forceinline__ void split_hl(float v, float& h, float& l) {
    __nv_bfloat16 bh = __float2bfloat16_rn(v);
    h = __bfloat162float(bh);
    l = v - h;
}
__device__ __forceinline__ void mma_bf16(float* c,
                                         uint32_t a0, uint32_t a1, uint32_t a2, uint32_t a3,
                                         uint32_t b0, uint32_t b1) {
    asm("mma.sync.aligned.m16n8k16.row.col.f32.bf16.bf16.f32 "
        "{%0,%1,%2,%3}, {%4,%5,%6,%7}, {%8,%9}, {%0,%1,%2,%3};"
        : "+f"(c[0]), "+f"(c[1]), "+f"(c[2]), "+f"(c[3])
        : "r"(a0), "r"(a1), "r"(a2), "r"(a3), "r"(b0), "r"(b1));
}

// SMEM layout. Stride 36 words: bank=(4q+r)%32 -> conflict-free fragments.
// A: 64 rows x 32 kpairs; B: 160 rows x 32 kpairs; each hi & lo.
#define ASTR 36
#define SM_BIAS 0
#define SM_A_HI 128
#define SM_A_LO (SM_A_HI + 64 * ASTR * 4)        //  9344
#define SM_B_HI (SM_A_LO + 64 * ASTR * 4)        // 18560
#define SM_B_LO (SM_B_HI + 160 * ASTR * 4)       // 41600
#define SMEM_BYTES (SM_B_LO + 160 * ASTR * 4)    // 64640

// ---------------------------------------------------------------------------
// mma.sync GEMM: CTA = 64 rows x 160 cols (half of N). 8 warps = 2(M) x 4(N);
// warp = 32 rows (2 m-tiles) x 40 cols (5 n-tiles). bf16x3 split precision.
// half = blockIdx.x & 1 (fixed per CTA so B is staged once).
// ---------------------------------------------------------------------------
template<int CA, int CB, bool RELU_A, int CIN_W>
__global__ __launch_bounds__(256, 2)
void gemm_mma(const float* __restrict__ xa, const float* __restrict__ xb,
              const float* __restrict__ W, const float* __restrict__ root,
              const float* __restrict__ bias,
              float* __restrict__ Y, float* __restrict__ agg, int n_nodes)
{
    extern __shared__ __align__(16) char smem[];
    uint32_t* Ah = reinterpret_cast<uint32_t*>(smem + SM_A_HI);
    uint32_t* Al = reinterpret_cast<uint32_t*>(smem + SM_A_LO);
    uint32_t* Bh = reinterpret_cast<uint32_t*>(smem + SM_B_HI);
    uint32_t* Bl = reinterpret_cast<uint32_t*>(smem + SM_B_LO);
    float*    bs = reinterpret_cast<float*>(smem + SM_BIAS);

    const int tid    = threadIdx.x;
    const int wid    = tid >> 5;
    const int lane   = tid & 31;
    const int warp_m = wid >> 2;        // 0..1 -> rows [32*warp_m, +32)
    const int warp_n = wid & 3;         // 0..3 -> cols [40*warp_n, +40)
    const int halfN  = blockIdx.x & 1;  // cols [160*halfN, +160)
    const int cbase  = halfN * 160;
    constexpr int KSTEPS = CIN_W / 16;

    // ---- Stage B once per CTA: local row r -> global out col cbase+r.
    for (int idx = tid; idx < 160 * 32; idx += 256) {
        const int r  = idx >> 5;
        const int kp = idx & 31;
        const int gc = cbase + r;
        const int i0 = 2 * kp, i1 = i0 + 1;
        float v0 = 0.0f, v1 = 0.0f;
        if (i0 < CIN_W) {
            if (gc < CKOUT) {
                const int kk = gc >> 5, cc = gc & 31;
                v0 = W[(kk * CIN_W + i0) * 32 + cc];
                v1 = W[(kk * CIN_W + i1) * 32 + cc];
            } else {
                v0 = root[i0 * 32 + (gc - CKOUT)];
                v1 = root[i1 * 32 + (gc - CKOUT)];
            }
        }
        float h0, l0, h1, l1;
        split_hl(v0, h0, l0); split_hl(v1, h1, l1);
        Bh[r * ASTR + kp] = pack_bf16(h0, h1);
        Bl[r * ASTR + kp] = pack_bf16(l0, l1);
    }
    if (tid < 32) bs[tid] = bias[tid];
    __syncthreads();

    const int ntiles = (n_nodes + 63) >> 6;
    const int tstep  = gridDim.x >> 1;

    for (int t = blockIdx.x >> 1; t < ntiles; t += tstep) {
        const int n0 = t << 6;

        // ---- Stage A tile: 64 rows x 32 k-pairs, hi/lo, relu/concat fused.
        for (int idx = tid; idx < 64 * 32; idx += 256) {
            const int row = idx >> 5;
            const int kp  = idx & 31;
            const int n   = n0 + row;
            const int i0  = 2 * kp, i1 = i0 + 1;
            float v0 = 0.0f, v1 = 0.0f;
            if (n < n_nodes) {
                if (i0 < CA) {
                    v0 = xa[(size_t)n * CA + i0];
                    v1 = xa[(size_t)n * CA + i1];
                    if (RELU_A) { v0 = fmaxf(v0, 0.0f); v1 = fmaxf(v1, 0.0f); }
                } else if (CB > 0 && i0 < CA + CB) {
                    v0 = xb[(size_t)n * CB + (i0 - CA)];
                    v1 = xb[(size_t)n * CB + (i1 - CA)];
                }
            }
            float h0, l0, h1, l1;
            split_hl(v0, h0, l0); split_hl(v1, h1, l1);
            Ah[row * ASTR + kp] = pack_bf16(h0, h1);
            Al[row * ASTR + kp] = pack_bf16(l0, l1);
        }
        __syncthreads();

        // ---- Compute: acc[2 m-tiles][5 n-tiles][4]
        float acc[2][5][4];
        #pragma unroll
        for (int mt = 0; mt < 2; mt++)
            #pragma unroll
            for (int nt = 0; nt < 5; nt++)
                #pragma unroll
                for (int j = 0; j < 4; j++) acc[mt][nt][j] = 0.0f;

        const int q   = lane >> 2;
        const int lkp = lane & 3;

        #pragma unroll
        for (int ks = 0; ks < KSTEPS; ks++) {
            const int kpb = ks * 8 + lkp;
            uint32_t ah[2][4], al[2][4];
            #pragma unroll
            for (int mt = 0; mt < 2; mt++) {
                const int g = warp_m * 32 + mt * 16 + q;
                ah[mt][0] = Ah[g * ASTR + kpb];
                ah[mt][1] = Ah[(g + 8) * ASTR + kpb];
                ah[mt][2] = Ah[g * ASTR + kpb + 4];
                ah[mt][3] = Ah[(g + 8) * ASTR + kpb + 4];
                al[mt][0] = Al[g * ASTR + kpb];
                al[mt][1] = Al[(g + 8) * ASTR + kpb];
                al[mt][2] = Al[g * ASTR + kpb + 4];
                al[mt][3] = Al[(g + 8) * ASTR + kpb + 4];
            }
            #pragma unroll
            for (int nt = 0; nt < 5; nt++) {
                const int nrow = warp_n * 40 + nt * 8 + q;
                const uint32_t bh0 = Bh[nrow * ASTR + kpb];
                const uint32_t bh1 = Bh[nrow * ASTR + kpb + 4];
                const uint32_t bl0 = Bl[nrow * ASTR + kpb];
                const uint32_t bl1 = Bl[nrow * ASTR + kpb + 4];
                #pragma unroll
                for (int mt = 0; mt < 2; mt++) {
                    mma_bf16(acc[mt][nt], ah[mt][0], ah[mt][1], ah[mt][2], ah[mt][3], bh0, bh1);
                    mma_bf16(acc[mt][nt], ah[mt][0], ah[mt][1], ah[mt][2], ah[mt][3], bl0, bl1);
                    mma_bf16(acc[mt][nt], al[mt][0], al[mt][1], al[mt][2], al[mt][3], bh0, bh1);
                }
            }
        }

        // ---- Epilogue: d0,d1 -> (row g, col0,col0+1); d2,d3 -> row g+8.
        #pragma unroll
        for (int mt = 0; mt < 2; mt++) {
            const int r0 = n0 + warp_m * 32 + mt * 16 + q;
            const int r1 = r0 + 8;
            #pragma unroll
            for (int nt = 0; nt < 5; nt++) {
                const int col0 = cbase + warp_n * 40 + nt * 8 + 2 * lkp;
                if (col0 < CKOUT) {
                    if (r0 < n_nodes)
                        *reinterpret_cast<float2*>(Y + (size_t)r0 * CKOUT + col0)
                            = make_float2(acc[mt][nt][0], acc[mt][nt][1]);
                    if (r1 < n_nodes)
                        *reinterpret_cast<float2*>(Y + (size_t)r1 * CKOUT + col0)
                            = make_float2(acc[mt][nt][2], acc[mt][nt][3]);
                } else {
                    const int a = col0 - CKOUT;
                    const float b0v = bs[a], b1v = bs[a + 1];
                    if (r0 < n_nodes)
                        *reinterpret_cast<float2*>(agg + (size_t)r0 * 32 + a)
                            = make_float2(acc[mt][nt][0] + b0v, acc[mt][nt][1] + b1v);
                    if (r1 < n_nodes)
                        *reinterpret_cast<float2*>(agg + (size_t)r1 * 32 + a)
                            = make_float2(acc[mt][nt][2] + b0v, acc[mt][nt][3] + b1v);
                }
            }
        }
        __syncthreads();
    }
}

// ---------------------------------------------------------------------------
// Counting sort of edges by src (once per launch, reused by 3 edge passes).
// ---------------------------------------------------------------------------
__global__ void hist_zero(int n) {
    const int i = blockIdx.x * blockDim.x + threadIdx.x;
    if (i < n) g_hist[i] = 0;
}
__global__ void hist_kernel(const int* __restrict__ ei, int n_edges) {
    const int e = blockIdx.x * blockDim.x + threadIdx.x;
    if (e < n_edges) atomicAdd(&g_hist[ei[e]], 1);
}
__global__ void scan1(int n) {
    __shared__ int s[512];
    const int tid = threadIdx.x;
    const int b   = blockIdx.x * 512 + tid;
    const int v   = (b < n) ? g_hist[b] : 0;
    s[tid] = v;
    __syncthreads();
    #pragma unroll
    for (int off = 1; off < 512; off <<= 1) {
        int t = (tid >= off) ? s[tid - off] : 0;
        __syncthreads();
        s[tid] += t;
        __syncthreads();
    }
    if (b < n) g_off[b] = s[tid] - v;        // exclusive, block-local
    if (tid == 511) g_bsum[blockIdx.x] = s[511];
}
// Parallel exclusive scan of up to 128 block sums (was a serial 1-thread loop).
__global__ void scan2(int nb) {
    __shared__ int s[128];
    const int tid = threadIdx.x;
    const int v = (tid < nb) ? g_bsum[tid] : 0;
    s[tid] = v;
    __syncthreads();
    #pragma unroll
    for (int off = 1; off < 128; off <<= 1) {
        int t = (tid >= off) ? s[tid - off] : 0;
        __syncthreads();
        s[tid] += t;
        __syncthreads();
    }
    if (tid < nb) g_bsum[tid] = s[tid] - v;  // exclusive
}
__global__ void scan3(int n) {
    const int b = blockIdx.x * 512 + threadIdx.x;
    if (b < n) g_off[b] += g_bsum[blockIdx.x];
}
__global__ void scatter_kernel(const int* __restrict__ ei,
                               const float* __restrict__ pseudo, int n_edges) {
    const int e = blockIdx.x * blockDim.x + threadIdx.x;
    if (e >= n_edges) return;
    const int src = ei[e];
    const int dst = ei[n_edges + e];
    const int pos = atomicAdd(&g_off[src], 1);
    g_se[pos] = make_int2(src, dst);
    g_sp[pos] = reinterpret_cast<const float2*>(pseudo)[e];
}

// ---------------------------------------------------------------------------
// Edge kernel (sorted by src): 8 lanes per edge, 4 channels per lane.
// ---------------------------------------------------------------------------
__global__ __launch_bounds__(256)
void edge_kernel(const float* __restrict__ Y, float* __restrict__ agg,
                 int n_edges, int n_nodes)
{
    const int t   = blockIdx.x * 256 + threadIdx.x;
    const int e   = t >> 3;
    const int sub = t & 7;
    if (e >= n_edges) return;

    const int2   sd = g_se[e];
    const float2 p  = g_sp[e];
    if ((unsigned)sd.x >= (unsigned)n_nodes || (unsigned)sd.y >= (unsigned)n_nodes) return;

    const float q00 = 0.5f * (1.0f - p.x) * (1.0f - p.x);
    const float q01 = -p.x * p.x + p.x + 0.5f;
    const float q02 = 0.5f * p.x * p.x;
    const float q10 = 0.5f * (1.0f - p.y) * (1.0f - p.y);
    const float q11 = -p.y * p.y + p.y + 0.5f;
    const float q12 = 0.5f * p.y * p.y;

    const float b0 = q10 * q00, b1 = q10 * q01, b2 = q10 * q02;
    const float b3 = q11 * q00, b4 = q11 * q01, b5 = q11 * q02;
    const float b6 = q12 * q00, b7 = q12 * q01, b8 = q12 * q02;

    const float4* y = reinterpret_cast<const float4*>(Y + (size_t)sd.x * CKOUT + sub * 4);
    const float4 y0 = y[0*8], y1 = y[1*8], y2 = y[2*8];
    const float4 y3 = y[3*8], y4 = y[4*8], y5 = y[5*8];
    const float4 y6 = y[6*8], y7 = y[7*8], y8 = y[8*8];

    float4 a;
    a.x = b0*y0.x + b1*y1.x + b2*y2.x + b3*y3.x + b4*y4.x + b5*y5.x + b6*y6.x + b7*y7.x + b8*y8.x;
    a.y = b0*y0.y + b1*y1.y + b2*y2.y + b3*y3.y + b4*y4.y + b5*y5.y + b6*y6.y + b7*y7.y + b8*y8.y;
    a.z = b0*y0.z + b1*y1.z + b2*y2.z + b3*y3.z + b4*y4.z + b5*y5.z + b6*y6.z + b7*y7.z + b8*y8.z;
    a.w = b0*y0.w + b1*y1.w + b2*y2.w + b3*y3.w + b4*y4.w + b5*y5.w + b6*y6.w + b7*y7.w + b8*y8.w;

    float* dp = agg + (size_t)sd.y * 32 + sub * 4;
    asm volatile("red.global.add.v4.f32 [%0], {%1, %2, %3, %4};"
                 :: "l"(dp), "f"(a.x), "f"(a.y), "f"(a.z), "f"(a.w) : "memory");
}

__global__ void relu_kernel(float* __restrict__ d, int n)
{
    const int i = blockIdx.x * blockDim.x + threadIdx.x;
    if (i < n) d[i] = fmaxf(d[i], 0.0f);
}

// ---------------------------------------------------------------------------
extern "C" void kernel_launch(void* const* d_in, const int* in_sizes, int n_in,
                              void* d_out, int out_size)
{
    const float* x      = (const float*)d_in[0];
    const int*   ei     = (const int*)d_in[1];     // int64 in ref -> int32 in harness
    const float* pseudo = (const float*)d_in[2];
    const float* skip   = (const float*)d_in[3];
    const float* W1     = (const float*)d_in[4];
    const float* root1  = (const float*)d_in[5];
    const float* b1     = (const float*)d_in[6];
    const float* W2     = (const float*)d_in[7];
    const float* root2  = (const float*)d_in[8];
    const float* b2     = (const float*)d_in[9];

    const int N = in_sizes[0] / 64;
    const int E = in_sizes[1] / 2;
    float* out = (float*)d_out;

    float *Y, *agg1, *agg2;
    cudaGetSymbolAddress((void**)&Y,    g_Y);
    cudaGetSymbolAddress((void**)&agg1, g_agg1);
    cudaGetSymbolAddress((void**)&agg2, g_agg2);

    cudaFuncSetAttribute(gemm_mma<64, 0,  false, 64>,
                         cudaFuncAttributeMaxDynamicSharedMemorySize, SMEM_BYTES);
    cudaFuncSetAttribute(gemm_mma<32, 32, true,  64>,
                         cudaFuncAttributeMaxDynamicSharedMemorySize, SMEM_BYTES);
    cudaFuncSetAttribute(gemm_mma<32, 0,  true,  32>,
                         cudaFuncAttributeMaxDynamicSharedMemorySize, SMEM_BYTES);

    const int gemm_grid = 296;          // 2 CTAs/SM; even halves
    const int edge_grid = (E * 8 + 255) / 256;
    const int NB        = (N + 511) / 512;

    // ---- Sort edges by src (once; reused by all 3 edge passes).
    hist_zero<<<NB, 512>>>(N);
    hist_kernel<<<(E + 255) / 256, 256>>>(ei, E);
    scan1<<<NB, 512>>>(N);
    scan2<<<1, 128>>>(NB);
    scan3<<<NB, 512>>>(N);
    scatter_kernel<<<(E + 255) / 256, 256>>>(ei, pseudo, E);

    // Layer 1: x[N,64] -> agg1
    gemm_mma<64, 0, false, 64><<<gemm_grid, 256, SMEM_BYTES>>>(x, nullptr, W1, root1, b1, Y, agg1, N);
    edge_kernel<<<edge_grid, 256>>>(Y, agg1, E, N);

    // Layer 2: concat(relu(agg1), skip)[N,64] -> agg2   (same W1/root1/b1)
    gemm_mma<32, 32, true, 64><<<gemm_grid, 256, SMEM_BYTES>>>(agg1, skip, W1, root1, b1, Y, agg2, N);
    edge_kernel<<<edge_grid, 256>>>(Y, agg2, E, N);

    // Layer 3: relu(agg2)[N,32] -> d_out  (K = 32 -> 2 k-steps)
    gemm_mma<32, 0, true, 32><<<gemm_grid, 256, SMEM_BYTES>>>(agg2, nullptr, W2, root2, b2, Y, out, N);
    edge_kernel<<<edge_grid, 256>>>(Y, out, E, N);

    relu_kernel<<<(N * 32 + 255) / 256, 256>>>(out, N * 32);
}

// round 9
// speedup vs baseline: 1.0524x; 1.0524x over previous
#include <cuda_runtime.h>
#include <cuda_bf16.h>
#include <cstdint>

// ---------------------------------------------------------------------------
// MeshUpConv: 3x SplineConv (kernel 3x3, degree 2, open spline) on GB300.
//
// R8 -> R9:
//   * GEMM geometry reverted to R7 (grid 148, 512 thr, 128x320 tile) -- the
//     N-split experiment regressed (duplicate A staging).
//   * Fragment loads via ldmatrix (.x4 for A, .x2 for B): 224 LDS.32 -> 96
//     LDSM per tile/warp, identical fragment layouts, conflict-free banks.
//   * scan2 launch removed: scan3 computes its own prefix of block sums.
// ---------------------------------------------------------------------------

#define NMAX  50000
#define EMAX  400000
#define CKOUT 288          // K * C_OUT = 9 * 32
#define NCOLS 320          // 288 Y cols + 32 self cols

__device__ float g_Y[(size_t)NMAX * CKOUT];
__device__ float g_agg1[(size_t)NMAX * 32];
__device__ float g_agg2[(size_t)NMAX * 32];

// sort scratch
__device__ int    g_hist[NMAX];
__device__ int    g_off[NMAX];
__device__ int    g_bsum[128];
__device__ int2   g_se[EMAX];     // sorted (src, dst)
__device__ float2 g_sp[EMAX];     // sorted pseudo

// ---- helpers --------------------------------------------------------------
__device__ __forceinline__ uint32_t pack_bf16(float a, float b) {
    __nv_bfloat162 t = __floats2bfloat162_rn(a, b);
    return *reinterpret_cast<uint32_t*>(&t);
}
__device__ __forceinline__ void split_hl(float v, float& h, float& l) {
    __nv_bfloat16 bh = __float2bfloat16_rn(v);
    h = __bfloat162float(bh);
    l = v - h;
}
__device__ __forceinline__ void mma_bf16(float* c,
                                         uint32_t a0, uint32_t a1, uint32_t a2, uint32_t a3,
                                         uint32_t b0, uint32_t b1) {
    asm("mma.sync.aligned.m16n8k16.row.col.f32.bf16.bf16.f32 "
        "{%0,%1,%2,%3}, {%4,%5,%6,%7}, {%8,%9}, {%0,%1,%2,%3};"
        : "+f"(c[0]), "+f"(c[1]), "+f"(c[2]), "+f"(c[3])
        : "r"(a0), "r"(a1), "r"(a2), "r"(a3), "r"(b0), "r"(b1));
}
__device__ __forceinline__ void ldsm_x4(uint32_t& r0, uint32_t& r1,
                                        uint32_t& r2, uint32_t& r3, uint32_t a) {
    asm volatile("ldmatrix.sync.aligned.m8n8.x4.shared.b16 {%0,%1,%2,%3}, [%4];"
                 : "=r"(r0), "=r"(r1), "=r"(r2), "=r"(r3) : "r"(a));
}
__device__ __forceinline__ void ldsm_x2(uint32_t& r0, uint32_t& r1, uint32_t a) {
    asm volatile("ldmatrix.sync.aligned.m8n8.x2.shared.b16 {%0,%1}, [%2];"
                 : "=r"(r0), "=r"(r1) : "r"(a));
}
__device__ __forceinline__ uint32_t smem_addr(const void* p) {
    return (uint32_t)__cvta_generic_to_shared(p);
}

// SMEM layout. Stride 36 words: bank=(4q+r)%32 -> conflict-free fragments.
// A: 128 rows x 32 kpairs; B: 320 rows x 32 kpairs; each hi & lo.
#define ASTR 36
#define SM_BIAS 0
#define SM_A_HI 128
#define SM_A_LO (SM_A_HI + 128 * ASTR * 4)       // 18560
#define SM_B_HI (SM_A_LO + 128 * ASTR * 4)       // 36992
#define SM_B_LO (SM_B_HI + 320 * ASTR * 4)       // 83072
#define SMEM_BYTES (SM_B_LO + 320 * ASTR * 4)    // 129152

// ---------------------------------------------------------------------------
// mma.sync GEMM: per 128-node tile, D[128, 320] = A[128,64] @ Bw[64,320].
// 16 warps = 4(M) x 4(N); warp = 32 rows (2 m-tiles) x 80 cols (10 n-tiles).
// bf16x3 split precision, fp32 accum. Fragments via ldmatrix.
// ---------------------------------------------------------------------------
template<int CA, int CB, bool RELU_A, int CIN_W>
__global__ __launch_bounds__(512)
void gemm_mma(const float* __restrict__ xa, const float* __restrict__ xb,
              const float* __restrict__ W, const float* __restrict__ root,
              const float* __restrict__ bias,
              float* __restrict__ Y, float* __restrict__ agg, int n_nodes)
{
    extern __shared__ __align__(16) char smem[];
    uint32_t* Ah = reinterpret_cast<uint32_t*>(smem + SM_A_HI);
    uint32_t* Al = reinterpret_cast<uint32_t*>(smem + SM_A_LO);
    uint32_t* Bh = reinterpret_cast<uint32_t*>(smem + SM_B_HI);
    uint32_t* Bl = reinterpret_cast<uint32_t*>(smem + SM_B_LO);
    float*    bs = reinterpret_cast<float*>(smem + SM_BIAS);

    const int tid    = threadIdx.x;
    const int wid    = tid >> 5;
    const int lane   = tid & 31;
    const int warp_m = wid >> 2;        // 0..3 -> rows [32*warp_m, +32)
    const int warp_n = wid & 3;         // 0..3 -> cols [80*warp_n, +80)
    constexpr int KSTEPS = CIN_W / 16;

    // ---- Stage B once per CTA: row r = output col, 32 k-pairs (k pad to 64).
    for (int idx = tid; idx < NCOLS * 32; idx += 512) {
        const int r  = idx >> 5;
        const int kp = idx & 31;
        const int i0 = 2 * kp, i1 = i0 + 1;
        float v0 = 0.0f, v1 = 0.0f;
        if (i0 < CIN_W) {
            if (r < CKOUT) {
                const int kk = r >> 5, cc = r & 31;
                v0 = W[(kk * CIN_W + i0) * 32 + cc];
                v1 = W[(kk * CIN_W + i1) * 32 + cc];
            } else {
                v0 = root[i0 * 32 + (r - CKOUT)];
                v1 = root[i1 * 32 + (r - CKOUT)];
            }
        }
        float h0, l0, h1, l1;
        split_hl(v0, h0, l0); split_hl(v1, h1, l1);
        Bh[r * ASTR + kp] = pack_bf16(h0, h1);
        Bl[r * ASTR + kp] = pack_bf16(l0, l1);
    }
    if (tid < 32) bs[tid] = bias[tid];
    __syncthreads();

    // ldmatrix per-lane base addresses (word offsets; +mt/ks/nt at use site).
    // A (.x4): lanes 0-7 (m0-7,k0-7), 8-15 (m8-15,k0-7), 16-23 (m0-7,k8-15),
    //          24-31 (m8-15,k8-15): row = base + (lane&15), +4 words if lane>=16.
    const uint32_t aoffw = (uint32_t)(warp_m * 32 + (lane & 15)) * ASTR + (lane >> 4) * 4;
    // B (.x2): lanes 0-7 (n0-7,k0-7), 8-15 (n0-7,k8-15).
    const uint32_t boffw = (uint32_t)(warp_n * 80 + (lane & 7)) * ASTR + ((lane >> 3) & 1) * 4;

    const uint32_t aH = smem_addr(Ah) + 4 * aoffw;
    const uint32_t aL = smem_addr(Al) + 4 * aoffw;
    const uint32_t bH = smem_addr(Bh) + 4 * boffw;
    const uint32_t bL = smem_addr(Bl) + 4 * boffw;

    const int ntiles = (n_nodes + 127) >> 7;

    for (int t = blockIdx.x; t < ntiles; t += gridDim.x) {
        const int n0 = t << 7;

        // ---- Stage A tile: 128 rows x 32 k-pairs, hi/lo, relu/concat fused.
        for (int idx = tid; idx < 128 * 32; idx += 512) {
            const int row = idx >> 5;
            const int kp  = idx & 31;
            const int n   = n0 + row;
            const int i0  = 2 * kp, i1 = i0 + 1;
            float v0 = 0.0f, v1 = 0.0f;
            if (n < n_nodes) {
                if (i0 < CA) {
                    v0 = xa[(size_t)n * CA + i0];
                    v1 = xa[(size_t)n * CA + i1];
                    if (RELU_A) { v0 = fmaxf(v0, 0.0f); v1 = fmaxf(v1, 0.0f); }
                } else if (CB > 0 && i0 < CA + CB) {
                    v0 = xb[(size_t)n * CB + (i0 - CA)];
                    v1 = xb[(size_t)n * CB + (i1 - CA)];
                }
            }
            float h0, l0, h1, l1;
            split_hl(v0, h0, l0); split_hl(v1, h1, l1);
            Ah[row * ASTR + kp] = pack_bf16(h0, h1);
            Al[row * ASTR + kp] = pack_bf16(l0, l1);
        }
        __syncthreads();

        // ---- Compute: acc[2 m-tiles][10 n-tiles][4]
        float acc[2][10][4];
        #pragma unroll
        for (int mt = 0; mt < 2; mt++)
            #pragma unroll
            for (int nt = 0; nt < 10; nt++)
                #pragma unroll
                for (int j = 0; j < 4; j++) acc[mt][nt][j] = 0.0f;

        #pragma unroll
        for (int ks = 0; ks < KSTEPS; ks++) {
            const uint32_t ko = 4u * ks * 8;         // bytes
            uint32_t ah[2][4], al[2][4];
            #pragma unroll
            for (int mt = 0; mt < 2; mt++) {
                const uint32_t mo = 4u * mt * 16 * ASTR;
                ldsm_x4(ah[mt][0], ah[mt][1], ah[mt][2], ah[mt][3], aH + mo + ko);
                ldsm_x4(al[mt][0], al[mt][1], al[mt][2], al[mt][3], aL + mo + ko);
            }
            #pragma unroll
            for (int nt = 0; nt < 10; nt++) {
                const uint32_t no = 4u * nt * 8 * ASTR;
                uint32_t bh0, bh1, bl0, bl1;
                ldsm_x2(bh0, bh1, bH + no + ko);
                ldsm_x2(bl0, bl1, bL + no + ko);
                #pragma unroll
                for (int mt = 0; mt < 2; mt++) {
                    mma_bf16(acc[mt][nt], ah[mt][0], ah[mt][1], ah[mt][2], ah[mt][3], bh0, bh1);
                    mma_bf16(acc[mt][nt], ah[mt][0], ah[mt][1], ah[mt][2], ah[mt][3], bl0, bl1);
                    mma_bf16(acc[mt][nt], al[mt][0], al[mt][1], al[mt][2], al[mt][3], bh0, bh1);
                }
            }
        }

        // ---- Epilogue: d0,d1 -> (row g, col0,col0+1); d2,d3 -> row g+8.
        const int q   = lane >> 2;
        const int lkp = lane & 3;
        #pragma unroll
        for (int mt = 0; mt < 2; mt++) {
            const int r0 = n0 + warp_m * 32 + mt * 16 + q;
            const int r1 = r0 + 8;
            #pragma unroll
            for (int nt = 0; nt < 10; nt++) {
                const int col0 = warp_n * 80 + nt * 8 + 2 * lkp;
                if (col0 < CKOUT) {
                    if (r0 < n_nodes)
                        *reinterpret_cast<float2*>(Y + (size_t)r0 * CKOUT + col0)
                            = make_float2(acc[mt][nt][0], acc[mt][nt][1]);
                    if (r1 < n_nodes)
                        *reinterpret_cast<float2*>(Y + (size_t)r1 * CKOUT + col0)
                            = make_float2(acc[mt][nt][2], acc[mt][nt][3]);
                } else {
                    const int a = col0 - CKOUT;
                    const float b0v = bs[a], b1v = bs[a + 1];
                    if (r0 < n_nodes)
                        *reinterpret_cast<float2*>(agg + (size_t)r0 * 32 + a)
                            = make_float2(acc[mt][nt][0] + b0v, acc[mt][nt][1] + b1v);
                    if (r1 < n_nodes)
                        *reinterpret_cast<float2*>(agg + (size_t)r1 * 32 + a)
                            = make_float2(acc[mt][nt][2] + b0v, acc[mt][nt][3] + b1v);
                }
            }
        }
        __syncthreads();
    }
}

// ---------------------------------------------------------------------------
// Counting sort of edges by src (once per launch, reused by 3 edge passes).
// ---------------------------------------------------------------------------
__global__ void hist_zero(int n) {
    const int i = blockIdx.x * blockDim.x + threadIdx.x;
    if (i < n) g_hist[i] = 0;
}
__global__ void hist_kernel(const int* __restrict__ ei, int n_edges) {
    const int e = blockIdx.x * blockDim.x + threadIdx.x;
    if (e < n_edges) atomicAdd(&g_hist[ei[e]], 1);
}
__global__ void scan1(int n) {
    __shared__ int s[512];
    const int tid = threadIdx.x;
    const int b   = blockIdx.x * 512 + tid;
    const int v   = (b < n) ? g_hist[b] : 0;
    s[tid] = v;
    __syncthreads();
    #pragma unroll
    for (int off = 1; off < 512; off <<= 1) {
        int t = (tid >= off) ? s[tid - off] : 0;
        __syncthreads();
        s[tid] += t;
        __syncthreads();
    }
    if (b < n) g_off[b] = s[tid] - v;        // exclusive, block-local
    if (tid == 511) g_bsum[blockIdx.x] = s[511];   // raw block total
}
// scan3 computes its own prefix over raw block sums (scan2 launch removed).
__global__ void scan3(int n) {
    __shared__ int pref;
    const int bid = blockIdx.x;
    if (threadIdx.x < 32) {
        int s = 0;
        for (int i = threadIdx.x; i < bid; i += 32) s += g_bsum[i];
        #pragma unroll
        for (int o = 16; o; o >>= 1) s += __shfl_down_sync(0xffffffffu, s, o);
        if (threadIdx.x == 0) pref = s;
    }
    __syncthreads();
    const int b = bid * 512 + threadIdx.x;
    if (b < n) g_off[b] += pref;
}
__global__ void scatter_kernel(const int* __restrict__ ei,
                               const float* __restrict__ pseudo, int n_edges) {
    const int e = blockIdx.x * blockDim.x + threadIdx.x;
    if (e >= n_edges) return;
    const int src = ei[e];
    const int dst = ei[n_edges + e];
    const int pos = atomicAdd(&g_off[src], 1);
    g_se[pos] = make_int2(src, dst);
    g_sp[pos] = reinterpret_cast<const float2*>(pseudo)[e];
}

// ---------------------------------------------------------------------------
// Edge kernel (sorted by src): 8 lanes per edge, 4 channels per lane.
// ---------------------------------------------------------------------------
__global__ __launch_bounds__(256)
void edge_kernel(const float* __restrict__ Y, float* __restrict__ agg,
                 int n_edges, int n_nodes)
{
    const int t   = blockIdx.x * 256 + threadIdx.x;
    const int e   = t >> 3;
    const int sub = t & 7;
    if (e >= n_edges) return;

    const int2   sd = g_se[e];
    const float2 p  = g_sp[e];
    if ((unsigned)sd.x >= (unsigned)n_nodes || (unsigned)sd.y >= (unsigned)n_nodes) return;

    const float q00 = 0.5f * (1.0f - p.x) * (1.0f - p.x);
    const float q01 = -p.x * p.x + p.x + 0.5f;
    const float q02 = 0.5f * p.x * p.x;
    const float q10 = 0.5f * (1.0f - p.y) * (1.0f - p.y);
    const float q11 = -p.y * p.y + p.y + 0.5f;
    const float q12 = 0.5f * p.y * p.y;

    const float b0 = q10 * q00, b1 = q10 * q01, b2 = q10 * q02;
    const float b3 = q11 * q00, b4 = q11 * q01, b5 = q11 * q02;
    const float b6 = q12 * q00, b7 = q12 * q01, b8 = q12 * q02;

    const float4* y = reinterpret_cast<const float4*>(Y + (size_t)sd.x * CKOUT + sub * 4);
    const float4 y0 = y[0*8], y1 = y[1*8], y2 = y[2*8];
    const float4 y3 = y[3*8], y4 = y[4*8], y5 = y[5*8];
    const float4 y6 = y[6*8], y7 = y[7*8], y8 = y[8*8];

    float4 a;
    a.x = b0*y0.x + b1*y1.x + b2*y2.x + b3*y3.x + b4*y4.x + b5*y5.x + b6*y6.x + b7*y7.x + b8*y8.x;
    a.y = b0*y0.y + b1*y1.y + b2*y2.y + b3*y3.y + b4*y4.y + b5*y5.y + b6*y6.y + b7*y7.y + b8*y8.y;
    a.z = b0*y0.z + b1*y1.z + b2*y2.z + b3*y3.z + b4*y4.z + b5*y5.z + b6*y6.z + b7*y7.z + b8*y8.z;
    a.w = b0*y0.w + b1*y1.w + b2*y2.w + b3*y3.w + b4*y4.w + b5*y5.w + b6*y6.w + b7*y7.w + b8*y8.w;

    float* dp = agg + (size_t)sd.y * 32 + sub * 4;
    asm volatile("red.global.add.v4.f32 [%0], {%1, %2, %3, %4};"
                 :: "l"(dp), "f"(a.x), "f"(a.y), "f"(a.z), "f"(a.w) : "memory");
}

__global__ void relu_kernel(float* __restrict__ d, int n)
{
    const int i = blockIdx.x * blockDim.x + threadIdx.x;
    if (i < n) d[i] = fmaxf(d[i], 0.0f);
}

// ---------------------------------------------------------------------------
extern "C" void kernel_launch(void* const* d_in, const int* in_sizes, int n_in,
                              void* d_out, int out_size)
{
    const float* x      = (const float*)d_in[0];
    const int*   ei     = (const int*)d_in[1];     // int64 in ref -> int32 in harness
    const float* pseudo = (const float*)d_in[2];
    const float* skip   = (const float*)d_in[3];
    const float* W1     = (const float*)d_in[4];
    const float* root1  = (const float*)d_in[5];
    const float* b1     = (const float*)d_in[6];
    const float* W2     = (const float*)d_in[7];
    const float* root2  = (const float*)d_in[8];
    const float* b2     = (const float*)d_in[9];

    const int N = in_sizes[0] / 64;
    const int E = in_sizes[1] / 2;
    float* out = (float*)d_out;

    float *Y, *agg1, *agg2;
    cudaGetSymbolAddress((void**)&Y,    g_Y);
    cudaGetSymbolAddress((void**)&agg1, g_agg1);
    cudaGetSymbolAddress((void**)&agg2, g_agg2);

    cudaFuncSetAttribute(gemm_mma<64, 0,  false, 64>,
                         cudaFuncAttributeMaxDynamicSharedMemorySize, SMEM_BYTES);
    cudaFuncSetAttribute(gemm_mma<32, 32, true,  64>,
                         cudaFuncAttributeMaxDynamicSharedMemorySize, SMEM_BYTES);
    cudaFuncSetAttribute(gemm_mma<32, 0,  true,  32>,
                         cudaFuncAttributeMaxDynamicSharedMemorySize, SMEM_BYTES);

    const int gemm_grid = 148;
    const int edge_grid = (E * 8 + 255) / 256;
    const int NB        = (N + 511) / 512;

    // ---- Sort edges by src (once; reused by all 3 edge passes).
    hist_zero<<<NB, 512>>>(N);
    hist_kernel<<<(E + 255) / 256, 256>>>(ei, E);
    scan1<<<NB, 512>>>(N);
    scan3<<<NB, 512>>>(N);
    scatter_kernel<<<(E + 255) / 256, 256>>>(ei, pseudo, E);

    // Layer 1: x[N,64] -> agg1
    gemm_mma<64, 0, false, 64><<<gemm_grid, 512, SMEM_BYTES>>>(x, nullptr, W1, root1, b1, Y, agg1, N);
    edge_kernel<<<edge_grid, 256>>>(Y, agg1, E, N);

    // Layer 2: concat(relu(agg1), skip)[N,64] -> agg2   (same W1/root1/b1)
    gemm_mma<32, 32, true, 64><<<gemm_grid, 512, SMEM_BYTES>>>(agg1, skip, W1, root1, b1, Y, agg2, N);
    edge_kernel<<<edge_grid, 256>>>(Y, agg2, E, N);

    // Layer 3: relu(agg2)[N,32] -> d_out  (K = 32 -> 2 k-steps)
    gemm_mma<32, 0, true, 32><<<gemm_grid, 512, SMEM_BYTES>>>(agg2, nullptr, W2, root2, b2, Y, out, N);
    edge_kernel<<<edge_grid, 256>>>(Y, out, E, N);

    relu_kernel<<<(N * 32 + 255) / 256, 256>>>(out, N * 32);
}